// round 4
// baseline (speedup 1.0000x reference)
#include <cuda_runtime.h>
#include <cuda_bf16.h>
#include <math.h>
#include <stdint.h>

// Problem constants (fixed by the reference)
#define INF   64
#define HID   128
#define LAT   32
#define HARM  8
#define NLAY  3
#define NG    64
#define NMAX  50000
#define EMAX  1600000

// ---------------- device scratch (no allocations allowed) ----------------
__device__ float g_bufA[NMAX * HID];
__device__ float g_bufB[NMAX * HID];
__device__ float g_dinv[NMAX];
__device__ int   g_deg[NMAX];
// bf16 hi/lo split weights, layout [k][o=128], k = i*16 + 2h + s
__device__ __nv_bfloat16 g_wbh_embed[INF * 16 * HID];
__device__ __nv_bfloat16 g_wbl_embed[INF * 16 * HID];
__device__ __nv_bfloat16 g_wbh_mp[NLAY][HID * 16 * HID];
__device__ __nv_bfloat16 g_wbl_mp[NLAY][HID * 16 * HID];
__device__ float g_wt_read[HID * HARM * 2 * LAT];
__device__ float g_pool[NG * HID];
__device__ float g_cnt[NG];
__device__ float g_y[NG * HID];

// ================= helpers =================
__device__ __forceinline__ uint32_t smem_u32(const void* p) {
    uint32_t a;
    asm("{ .reg .u64 t; cvta.to.shared.u64 t, %1; cvt.u32.u64 %0, t; }" : "=r"(a) : "l"(p));
    return a;
}

#define LDSM4(r, addr) \
    asm volatile("ldmatrix.sync.aligned.m8n8.x4.shared.b16 {%0,%1,%2,%3}, [%4];" \
        : "=r"((r)[0]), "=r"((r)[1]), "=r"((r)[2]), "=r"((r)[3]) : "r"(addr))
#define LDSM4T(r, addr) \
    asm volatile("ldmatrix.sync.aligned.m8n8.x4.trans.shared.b16 {%0,%1,%2,%3}, [%4];" \
        : "=r"((r)[0]), "=r"((r)[1]), "=r"((r)[2]), "=r"((r)[3]) : "r"(addr))
#define MMA16816(d, a, b0, b1) \
    asm volatile("mma.sync.aligned.m16n8k16.row.col.f32.bf16.bf16.f32 " \
        "{%0,%1,%2,%3}, {%4,%5,%6,%7}, {%8,%9}, {%0,%1,%2,%3};" \
        : "+f"((d)[0]), "+f"((d)[1]), "+f"((d)[2]), "+f"((d)[3]) \
        : "r"((a)[0]), "r"((a)[1]), "r"((a)[2]), "r"((a)[3]), "r"(b0), "r"(b1))

// ---------------- weight prep: hi/lo bf16 split into [k][o] ----------------
__global__ void prep_wb(const float* __restrict__ W, __nv_bfloat16* __restrict__ Whi,
                        __nv_bfloat16* __restrict__ Wlo, int K, int IN_F) {
    int idx = blockIdx.x * blockDim.x + threadIdx.x;
    if (idx >= K * HID) return;
    int o = idx & (HID - 1);
    int k = idx >> 7;
    int s = k & 1;
    int h = (k >> 1) & (HARM - 1);
    int i = k >> 4;
    float w = W[(((size_t)s * HID + o) * IN_F + i) * HARM + h];
    __nv_bfloat16 hi = __float2bfloat16(w);
    Whi[idx] = hi;
    Wlo[idx] = __float2bfloat16(w - __bfloat162float(hi));
}
// readout weights transpose: Wt[k][o], o fastest
__global__ void transpose_w(const float* __restrict__ W, float* __restrict__ Wt,
                            int OUT, int IN_F) {
    int idx = blockIdx.x * blockDim.x + threadIdx.x;
    int total = 2 * OUT * IN_F * HARM;
    if (idx >= total) return;
    int o = idx % OUT;
    int k = idx / OUT;
    int s = k & 1;
    int h = (k >> 1) & (HARM - 1);
    int i = k >> 4;
    Wt[idx] = W[(((size_t)s * OUT + o) * IN_F + i) * HARM + h];
}

// ---------------- degree / dinv ----------------
__global__ void deg_kernel(const int* __restrict__ ei, int* __restrict__ deg, int E) {
    int e = blockIdx.x * blockDim.x + threadIdx.x;
    if (e < E) atomicAdd(&deg[ei[E + e]], 1);
}
__global__ void dinv_kernel(const int* __restrict__ deg, float* __restrict__ dinv, int n) {
    int i = blockIdx.x * blockDim.x + threadIdx.x;
    if (i < n) dinv[i] = rsqrtf((float)(deg[i] + 1));
}

// ---------------- bf16 mma.sync KAN GEMM ----------------
// Y[N,128] = Phi(X)[N, K] @ W^T via 3-pass bf16 split (hi*hi + hi*lo + lo*hi).
// CTA tile 128x128, 8 warps (4 along m x 2 along n), warp tile 32x64.
// K staged in chunks of 32 (2 features).
#define A_STRIDE 80          // 128 rows x (64B data + 16B pad)
#define B_STRIDE 272         // 32 k-rows x (256B data + 16B pad)

template <int KF>
__launch_bounds__(256, 1)
__global__ void kan_gemm_mma(const float* __restrict__ X,
                             const __nv_bfloat16* __restrict__ Bhi,
                             const __nv_bfloat16* __restrict__ Blo,
                             float* __restrict__ Y, int n) {
    __shared__ __align__(16) char s_a_hi[128 * A_STRIDE];
    __shared__ __align__(16) char s_a_lo[128 * A_STRIDE];
    __shared__ __align__(16) char s_b_hi[32 * B_STRIDE];
    __shared__ __align__(16) char s_b_lo[32 * B_STRIDE];

    const int tid  = threadIdx.x;
    const int lane = tid & 31;
    const int wid  = tid >> 5;
    const int wm   = (wid & 3) * 32;   // warp m offset
    const int wn   = (wid >> 2) * 64;  // warp n offset
    const int bm   = blockIdx.x * 128;

    const uint32_t aHi = smem_u32(s_a_hi);
    const uint32_t aLo = smem_u32(s_a_lo);
    const uint32_t bHi = smem_u32(s_b_hi);
    const uint32_t bLo = smem_u32(s_b_lo);

    // Phi generation mapping: 128 rows x 2 features
    const int grow  = tid & 127;
    const int gfeat = tid >> 7;
    const int gm    = bm + grow;
    const bool gvalid = (gm < n);
    const float* xrow = X + (size_t)gm * KF;

    float acc[2][8][4];
#pragma unroll
    for (int i = 0; i < 2; i++)
#pragma unroll
        for (int j = 0; j < 8; j++)
#pragma unroll
            for (int q = 0; q < 4; q++) acc[i][j][q] = 0.f;

    constexpr int NCH = KF / 2;
    for (int c = 0; c < NCH; c++) {
        // ---- generate Phi hi/lo for feature c*2+gfeat ----
        {
            float x = gvalid ? xrow[c * 2 + gfeat] : 0.f;
            float s1, c1;
            sincosf(x, &s1, &c1);
            float v[16];
            float cp = 1.f, sp = 0.f, cc = c1, sc = s1;
#pragma unroll
            for (int h = 0; h < 8; h++) {
                v[2 * h] = cc; v[2 * h + 1] = sc;
                float cn = 2.f * c1 * cc - cp;
                float sn = 2.f * c1 * sc - sp;
                cp = cc; sp = sc; cc = cn; sc = sn;
            }
            uint32_t hi[8], lo[8];
#pragma unroll
            for (int j = 0; j < 8; j++) {
                __nv_bfloat16 h0 = __float2bfloat16(v[2 * j]);
                __nv_bfloat16 h1 = __float2bfloat16(v[2 * j + 1]);
                float l0 = v[2 * j] - __bfloat162float(h0);
                float l1 = v[2 * j + 1] - __bfloat162float(h1);
                __nv_bfloat162 hp; hp.x = h0; hp.y = h1;
                __nv_bfloat162 lp; lp.x = __float2bfloat16(l0); lp.y = __float2bfloat16(l1);
                hi[j] = *(uint32_t*)&hp;
                lo[j] = *(uint32_t*)&lp;
            }
            int off = grow * A_STRIDE + gfeat * 32;
            *(uint4*)(s_a_hi + off)      = make_uint4(hi[0], hi[1], hi[2], hi[3]);
            *(uint4*)(s_a_hi + off + 16) = make_uint4(hi[4], hi[5], hi[6], hi[7]);
            *(uint4*)(s_a_lo + off)      = make_uint4(lo[0], lo[1], lo[2], lo[3]);
            *(uint4*)(s_a_lo + off + 16) = make_uint4(lo[4], lo[5], lo[6], lo[7]);
        }
        // ---- stage B tile (32 k-rows x 128 o), hi and lo ----
        {
            const uint4* srcH = (const uint4*)(Bhi) + (size_t)c * 512;
            const uint4* srcL = (const uint4*)(Blo) + (size_t)c * 512;
#pragma unroll
            for (int j = 0; j < 2; j++) {
                int lin = tid + j * 256;          // 0..511 (uint4 units)
                int kr  = lin >> 4;               // 16 uint4 per 256B row
                int off = lin & 15;
                *(uint4*)(s_b_hi + kr * B_STRIDE + off * 16) = srcH[lin];
                *(uint4*)(s_b_lo + kr * B_STRIDE + off * 16) = srcL[lin];
            }
        }
        __syncthreads();

        // ---- 2 x k16 steps ----
#pragma unroll
        for (int ks = 0; ks < 2; ks++) {
            uint32_t ah[2][4], al[2][4], bh[4][4], bl[4][4];
            const uint32_t arow = (wm + (lane & 15)) * A_STRIDE + ks * 32 + ((lane >> 4) << 4);
#pragma unroll
            for (int msub = 0; msub < 2; msub++) {
                uint32_t d = arow + msub * 16 * A_STRIDE;
                LDSM4(ah[msub], aHi + d);
                LDSM4(al[msub], aLo + d);
            }
            const uint32_t brow = (ks * 16 + (lane & 15)) * B_STRIDE + (wn + ((lane >> 4) << 3)) * 2;
#pragma unroll
            for (int bs = 0; bs < 4; bs++) {
                uint32_t d = brow + bs * 32;
                LDSM4T(bh[bs], bHi + d);
                LDSM4T(bl[bs], bLo + d);
            }
            // pass 1: hi*hi
#pragma unroll
            for (int msub = 0; msub < 2; msub++)
#pragma unroll
                for (int nf = 0; nf < 8; nf++)
                    MMA16816(acc[msub][nf], ah[msub], bh[nf >> 1][(nf & 1) * 2], bh[nf >> 1][(nf & 1) * 2 + 1]);
            // pass 2: hi*lo
#pragma unroll
            for (int msub = 0; msub < 2; msub++)
#pragma unroll
                for (int nf = 0; nf < 8; nf++)
                    MMA16816(acc[msub][nf], ah[msub], bl[nf >> 1][(nf & 1) * 2], bl[nf >> 1][(nf & 1) * 2 + 1]);
            // pass 3: lo*hi
#pragma unroll
            for (int msub = 0; msub < 2; msub++)
#pragma unroll
                for (int nf = 0; nf < 8; nf++)
                    MMA16816(acc[msub][nf], al[msub], bh[nf >> 1][(nf & 1) * 2], bh[nf >> 1][(nf & 1) * 2 + 1]);
        }
        __syncthreads();
    }

    // ---- epilogue ----
#pragma unroll
    for (int msub = 0; msub < 2; msub++) {
        int r0 = bm + wm + msub * 16 + (lane >> 2);
        int cbase = wn + (lane & 3) * 2;
#pragma unroll
        for (int nf = 0; nf < 8; nf++) {
            int col = cbase + nf * 8;
            if (r0 < n) {
                *(float2*)(Y + (size_t)r0 * HID + col) = make_float2(acc[msub][nf][0], acc[msub][nf][1]);
            }
            if (r0 + 8 < n) {
                *(float2*)(Y + (size_t)(r0 + 8) * HID + col) = make_float2(acc[msub][nf][2], acc[msub][nf][3]);
            }
        }
    }
}

// ---------------- scatter: dst[col] += dinv[row]*dinv[col] * src[row] ------
__global__ void scatter_kernel(const float* __restrict__ src, float* __restrict__ dst,
                               const int* __restrict__ ei, const float* __restrict__ dinv,
                               int E, int Etot) {
    int gw   = (blockIdx.x * blockDim.x + threadIdx.x) >> 5;
    int lane = threadIdx.x & 31;
    if (gw >= Etot) return;
    int r, c;
    if (gw < E) { r = ei[gw]; c = ei[E + gw]; }
    else        { r = c = gw - E; }
    float nrm = dinv[r] * dinv[c];
    float4 v = ((const float4*)(src + (size_t)r * HID))[lane];
    float* d = dst + (size_t)c * HID + lane * 4;
    atomicAdd(d + 0, nrm * v.x);
    atomicAdd(d + 1, nrm * v.y);
    atomicAdd(d + 2, nrm * v.z);
    atomicAdd(d + 3, nrm * v.w);
}

// ---------------- mean pool ----------------
__global__ void pool_kernel(const float* __restrict__ h, const int* __restrict__ batch,
                            float* __restrict__ pool, float* __restrict__ cnt, int n) {
    int c  = threadIdx.x;
    int n0 = blockIdx.x * 256;
    if (n0 >= n) return;
    int nend = min(n0 + 256, n);
    float acc = 0.f;
    int cur = batch[n0];
    int runStart = n0;
    for (int m = n0; m < nend; m++) {
        int b = batch[m];
        if (b != cur) {
            atomicAdd(&pool[cur * HID + c], acc);
            if (c == 0) atomicAdd(&cnt[cur], (float)(m - runStart));
            acc = 0.f; cur = b; runStart = m;
        }
        acc += h[(size_t)m * HID + c];
    }
    atomicAdd(&pool[cur * HID + c], acc);
    if (c == 0) atomicAdd(&cnt[cur], (float)(nend - runStart));
}

__global__ void mean_kernel(const float* __restrict__ pool, const float* __restrict__ cnt,
                            float* __restrict__ y) {
    int idx = blockIdx.x * blockDim.x + threadIdx.x;
    if (idx >= NG * HID) return;
    int g = idx >> 7;
    y[idx] = pool[idx] / fmaxf(cnt[g], 1.0f);
}

// ---------------- readout KAN: [64,128] -> [64,32] -------------------------
__global__ void kan_read_kernel(const float* __restrict__ Y, const float* __restrict__ Wt,
                                float* __restrict__ out) {
    int idx = blockIdx.x * blockDim.x + threadIdx.x;
    if (idx >= NG * LAT) return;
    int g = idx >> 5;
    int o = idx & 31;
    float acc = 0.f;
    for (int i = 0; i < HID; i++) {
        float x = Y[g * HID + i];
        float s1, c1;
        sincosf(x, &s1, &c1);
        float cp = 1.f, sp = 0.f, cc = c1, sc = s1;
#pragma unroll
        for (int h = 0; h < HARM; h++) {
            const float* w = Wt + ((size_t)(i * HARM + h) * 2) * LAT;
            acc = fmaf(cc, w[o], acc);
            acc = fmaf(sc, w[LAT + o], acc);
            float cn = 2.f * c1 * cc - cp;
            float sn = 2.f * c1 * sc - sp;
            cp = cc; sp = sc; cc = cn; sc = sn;
        }
    }
    out[idx] = acc;
}

// ---------------- launch ----------------------------------------------------
extern "C" void kernel_launch(void* const* d_in, const int* in_sizes, int n_in,
                              void* d_out, int out_size) {
    const float* features = (const float*)d_in[0];
    const int*   ei       = (const int*)d_in[1];
    const int*   batch    = (const int*)d_in[2];
    const float* W_embed  = (const float*)d_in[3];
    const float* W_mp     = (const float*)d_in[4];
    const float* W_read   = (const float*)d_in[5];
    float*       out      = (float*)d_out;

    const int n = in_sizes[0] / INF;
    const int E = in_sizes[1] / 2;
    const int Etot = E + n;

    float *p_bufA, *p_bufB, *p_dinv, *p_pool, *p_cnt, *p_y, *p_wtr;
    __nv_bfloat16 *p_weh, *p_wel, *p_wmh, *p_wml;
    int *p_deg;
    cudaGetSymbolAddress((void**)&p_bufA, g_bufA);
    cudaGetSymbolAddress((void**)&p_bufB, g_bufB);
    cudaGetSymbolAddress((void**)&p_dinv, g_dinv);
    cudaGetSymbolAddress((void**)&p_deg,  g_deg);
    cudaGetSymbolAddress((void**)&p_weh,  g_wbh_embed);
    cudaGetSymbolAddress((void**)&p_wel,  g_wbl_embed);
    cudaGetSymbolAddress((void**)&p_wmh,  g_wbh_mp);
    cudaGetSymbolAddress((void**)&p_wml,  g_wbl_mp);
    cudaGetSymbolAddress((void**)&p_wtr,  g_wt_read);
    cudaGetSymbolAddress((void**)&p_pool, g_pool);
    cudaGetSymbolAddress((void**)&p_cnt,  g_cnt);
    cudaGetSymbolAddress((void**)&p_y,    g_y);

    // 1) weight prep (bf16 hi/lo split, [k][o] layout)
    {
        int tot = INF * 16 * HID;
        prep_wb<<<(tot + 255) / 256, 256>>>(W_embed, p_weh, p_wel, INF * 16, INF);
    }
    for (int l = 0; l < NLAY; l++) {
        int tot = HID * 16 * HID;
        prep_wb<<<(tot + 255) / 256, 256>>>(W_mp + (size_t)l * 2 * HID * HID * HARM,
                                            p_wmh + (size_t)l * tot,
                                            p_wml + (size_t)l * tot, HID * 16, HID);
    }
    {
        int tot = 2 * LAT * HID * HARM;
        transpose_w<<<(tot + 255) / 256, 256>>>(W_read, p_wtr, LAT, HID);
    }

    // 2) degrees -> dinv
    cudaMemsetAsync(p_deg, 0, (size_t)n * sizeof(int));
    deg_kernel<<<(E + 255) / 256, 256>>>(ei, p_deg, E);
    dinv_kernel<<<(n + 255) / 256, 256>>>(p_deg, p_dinv, n);

    // 3) embedding KAN (tensor cores via mma.sync)
    int gblocks = (n + 127) / 128;
    kan_gemm_mma<INF><<<gblocks, 256>>>(features, p_weh, p_wel, p_bufA, n);

    // 4) message-passing layers
    for (int l = 0; l < NLAY; l++) {
        size_t woff = (size_t)l * HID * 16 * HID;
        kan_gemm_mma<HID><<<gblocks, 256>>>(p_bufA, p_wmh + woff, p_wml + woff, p_bufB, n);
        cudaMemsetAsync(p_bufA, 0, (size_t)n * HID * sizeof(float));
        scatter_kernel<<<(Etot + 7) / 8, 256>>>(p_bufB, p_bufA, ei, p_dinv, E, Etot);
    }

    // 5) mean pool + readout
    cudaMemsetAsync(p_pool, 0, NG * HID * sizeof(float));
    cudaMemsetAsync(p_cnt,  0, NG * sizeof(float));
    pool_kernel<<<(n + 255) / 256, 128>>>(p_bufA, batch, p_pool, p_cnt, n);
    mean_kernel<<<(NG * HID + 255) / 256, 256>>>(p_pool, p_cnt, p_y);
    kan_read_kernel<<<(NG * LAT + 255) / 256, 256>>>(p_y, p_wtr, out);
}